// round 1
// baseline (speedup 1.0000x reference)
#include <cuda_runtime.h>
#include <math.h>

#define Bb 16
#define LL 2048
#define HID 4096
#define CQ 1536
#define CKV 512
#define HH 32
#define DH 128
#define DR 64
#define HDR (HH*DR)   // 2048
#define HDH (HH*DH)   // 4096
#define L1P (LL+1)    // 2049

// out layout: [output 16*4096][new_cKV 16*2049*512][new_kR 16*2049*2048]
#define OFF_CKV (Bb*HID)                        // 65536
#define OFF_KR  (OFF_CKV + Bb*L1P*CKV)          // 16850944

// ---------------- scratch (device globals, allocation-free) ----------------
__device__ __align__(16) float g_cQ  [Bb*CQ];
__device__ __align__(16) float g_qC  [Bb*HDH];
__device__ __align__(16) float g_qR  [Bb*HDR];
__device__ __align__(16) float g_kRn [Bb*HDR];
__device__ __align__(16) float g_cKVn[Bb*CKV];
__device__ __align__(16) float g_qCeff[Bb*CKV];
__device__ __align__(16) float g_scores[Bb*L1P];
__device__ __align__(16) float g_probs [Bb*L1P];
__device__ __align__(16) float g_wsum[Bb*CKV];
__device__ __align__(16) float g_v   [Bb*HDH];

// ---------------- zero scratch + output head region ----------------
__global__ void zero_kernel(float* __restrict__ out) {
    int t = blockIdx.x * blockDim.x + threadIdx.x;
    int T = gridDim.x * blockDim.x;
    for (int i = t; i < Bb*CQ;  i += T) g_cQ[i]  = 0.f;
    for (int i = t; i < Bb*HDH; i += T) g_qC[i]  = 0.f;
    for (int i = t; i < Bb*HDR; i += T) g_qR[i]  = 0.f;
    for (int i = t; i < Bb*HDR; i += T) g_kRn[i] = 0.f;
    for (int i = t; i < Bb*CKV; i += T) g_cKVn[i]= 0.f;
    for (int i = t; i < Bb*CKV; i += T) g_wsum[i]= 0.f;
    for (int i = t; i < Bb*HDH; i += T) g_v[i]   = 0.f;
    for (int i = t; i < Bb*HID; i += T) out[i]   = 0.f;
}

// ---------------- generic split-K skinny GEMM: out[16,N] += X[16,K] @ W[K,N] ----------------
// block: 128 threads, each thread 4 consecutive columns (512 cols/block).
// grid: (N/512, K/Kper). Kper multiple of 32. Partials accumulated via atomicAdd.
__global__ void gemm_xw(const float* __restrict__ X, const float* __restrict__ W,
                        float* __restrict__ out, int K, int N, int Kper)
{
    __shared__ float4 s4[32*4];           // 32 k-slices x 16 batch values
    float* s = reinterpret_cast<float*>(s4);
    int n = (blockIdx.x * blockDim.x + threadIdx.x) * 4;
    int kb = blockIdx.y * Kper;
    float4 acc[16];
#pragma unroll
    for (int b = 0; b < 16; b++) acc[b] = make_float4(0.f, 0.f, 0.f, 0.f);

    for (int k0 = kb; k0 < kb + Kper; k0 += 32) {
        for (int i = threadIdx.x; i < 512; i += blockDim.x) {
            int b = i >> 5, k = i & 31;
            s[k * 16 + b] = X[b * K + k0 + k];
        }
        __syncthreads();
        if (n < N) {
            const float* Wp = W + (size_t)k0 * N + n;
#pragma unroll
            for (int k = 0; k < 32; k++) {
                float4 w4 = *reinterpret_cast<const float4*>(Wp + (size_t)k * N);
                float4 x0 = s4[k*4+0], x1 = s4[k*4+1], x2 = s4[k*4+2], x3 = s4[k*4+3];
                float xs[16];
                *reinterpret_cast<float4*>(&xs[0])  = x0;
                *reinterpret_cast<float4*>(&xs[4])  = x1;
                *reinterpret_cast<float4*>(&xs[8])  = x2;
                *reinterpret_cast<float4*>(&xs[12]) = x3;
#pragma unroll
                for (int b = 0; b < 16; b++) {
                    float xb = xs[b];
                    acc[b].x = fmaf(xb, w4.x, acc[b].x);
                    acc[b].y = fmaf(xb, w4.y, acc[b].y);
                    acc[b].z = fmaf(xb, w4.z, acc[b].z);
                    acc[b].w = fmaf(xb, w4.w, acc[b].w);
                }
            }
        }
        __syncthreads();
    }
    if (n < N) {
#pragma unroll
        for (int b = 0; b < 16; b++) {
            atomicAdd(&out[b * N + n + 0], acc[b].x);
            atomicAdd(&out[b * N + n + 1], acc[b].y);
            atomicAdd(&out[b * N + n + 2], acc[b].z);
            atomicAdd(&out[b * N + n + 3], acc[b].w);
        }
    }
}

// ---------------- qC_eff[b,n] = dot(qC[b,:4096], W_UK_C[n,:4096]) ----------------
// grid (64, 16), block 256 (8 warps; warp -> one n)
__global__ void qceff_kernel(const float* __restrict__ Wukc) {
    int b = blockIdx.y;
    int wid = threadIdx.x >> 5, lane = threadIdx.x & 31;
    __shared__ float4 sq[HDH / 4];        // 16 KB
    for (int i = threadIdx.x; i < HDH / 4; i += blockDim.x)
        sq[i] = reinterpret_cast<const float4*>(g_qC + b * HDH)[i];
    __syncthreads();
    int n = blockIdx.x * 8 + wid;
    const float4* w4 = reinterpret_cast<const float4*>(Wukc + (size_t)n * HDH);
    float sum = 0.f;
    for (int j = lane; j < HDH / 4; j += 32) {
        float4 a = sq[j], w = w4[j];
        sum += a.x * w.x + a.y * w.y + a.z * w.z + a.w * w.w;
    }
#pragma unroll
    for (int o = 16; o; o >>= 1) sum += __shfl_xor_sync(0xffffffffu, sum, o);
    if (lane == 0) g_qCeff[b * CKV + n] = sum;
}

// ---------------- fused: prefix scores + cache concat/copy ----------------
// grid (256, 16), block 256 (8 warps; warp -> one l row)
__global__ void score_copy(const float* __restrict__ cKV, const float* __restrict__ kRc,
                           float* __restrict__ out)
{
    int b = blockIdx.y;
    int wid = threadIdx.x >> 5, lane = threadIdx.x & 31;
    __shared__ float4 sq[(CKV + HDR) / 4];   // 10 KB: [qCeff | qR]
    for (int i = threadIdx.x; i < CKV / 4; i += blockDim.x)
        sq[i] = reinterpret_cast<const float4*>(g_qCeff + b * CKV)[i];
    for (int i = threadIdx.x; i < HDR / 4; i += blockDim.x)
        sq[CKV / 4 + i] = reinterpret_cast<const float4*>(g_qR + b * HDR)[i];
    __syncthreads();

    int l = blockIdx.x * 8 + wid;
    const float4* c4  = reinterpret_cast<const float4*>(cKV + ((size_t)b * LL + l) * CKV);
    const float4* r4  = reinterpret_cast<const float4*>(kRc + ((size_t)b * LL + l) * HDR);
    float4* oc = reinterpret_cast<float4*>(out + (size_t)OFF_CKV + ((size_t)b * L1P + l) * CKV);
    float4* orr= reinterpret_cast<float4*>(out + (size_t)OFF_KR  + ((size_t)b * L1P + l) * HDR);

    float sum = 0.f;
#pragma unroll
    for (int j = 0; j < (CKV / 4) / 32; j++) {    // 4
        int idx = lane + j * 32;
        float4 v = c4[idx]; oc[idx] = v;
        float4 q = sq[idx];
        sum += v.x * q.x + v.y * q.y + v.z * q.z + v.w * q.w;
    }
#pragma unroll
    for (int j = 0; j < (HDR / 4) / 32; j++) {    // 16
        int idx = lane + j * 32;
        float4 v = r4[idx]; orr[idx] = v;
        float4 q = sq[CKV / 4 + idx];
        sum += v.x * q.x + v.y * q.y + v.z * q.z + v.w * q.w;
    }
#pragma unroll
    for (int o = 16; o; o >>= 1) sum += __shfl_xor_sync(0xffffffffu, sum, o);
    if (lane == 0) g_scores[b * L1P + l] = sum;
}

// ---------------- new-token score + write new cache rows ----------------
__global__ void newtoken_kernel(float* __restrict__ out) {
    int b = blockIdx.x, tid = threadIdx.x;
    __shared__ float red[256];
    float sum = 0.f;
    for (int i = tid; i < CKV; i += 256) {
        float v = g_cKVn[b * CKV + i];
        out[(size_t)OFF_CKV + ((size_t)b * L1P + LL) * CKV + i] = v;
        sum += v * g_qCeff[b * CKV + i];
    }
    for (int i = tid; i < HDR; i += 256) {
        float v = g_kRn[b * HDR + i];
        out[(size_t)OFF_KR + ((size_t)b * L1P + LL) * HDR + i] = v;
        sum += v * g_qR[b * HDR + i];
    }
    red[tid] = sum; __syncthreads();
    for (int s = 128; s; s >>= 1) { if (tid < s) red[tid] += red[tid + s]; __syncthreads(); }
    if (tid == 0) g_scores[b * L1P + LL] = red[0];
}

// ---------------- softmax over 2049 (with 1/sqrt(192) scale) ----------------
__global__ void softmax_kernel() {
    int b = blockIdx.x, tid = threadIdx.x;
    __shared__ float red[256];
    const float scale = rsqrtf((float)(DH + DR));
    float m = -1e30f;
    for (int i = tid; i < L1P; i += 256) m = fmaxf(m, g_scores[b * L1P + i] * scale);
    red[tid] = m; __syncthreads();
    for (int s = 128; s; s >>= 1) { if (tid < s) red[tid] = fmaxf(red[tid], red[tid + s]); __syncthreads(); }
    m = red[0]; __syncthreads();
    float sum = 0.f;
    for (int i = tid; i < L1P; i += 256) {
        float e = expf(g_scores[b * L1P + i] * scale - m);
        g_probs[b * L1P + i] = e;
        sum += e;
    }
    red[tid] = sum; __syncthreads();
    for (int s = 128; s; s >>= 1) { if (tid < s) red[tid] += red[tid + s]; __syncthreads(); }
    float inv = 1.f / red[0];
    __syncthreads();
    for (int i = tid; i < L1P; i += 256) g_probs[b * L1P + i] *= inv;
}

// ---------------- probs-weighted cKV sum (incl. new token) ----------------
// grid (16 b, 16 l-splits), block 128: thread -> 4 consecutive d
__global__ void wsum_kernel(const float* __restrict__ cKV) {
    int b = blockIdx.x, ls = blockIdx.y, tid = threadIdx.x;
    const float4* c4 = reinterpret_cast<const float4*>(cKV + (size_t)b * LL * CKV);
    float4 acc = make_float4(0.f, 0.f, 0.f, 0.f);
    int l0 = ls * (LL / 16);
#pragma unroll 4
    for (int l = l0; l < l0 + LL / 16; l++) {
        float p = g_probs[b * L1P + l];
        float4 v = c4[(size_t)l * (CKV / 4) + tid];
        acc.x = fmaf(p, v.x, acc.x); acc.y = fmaf(p, v.y, acc.y);
        acc.z = fmaf(p, v.z, acc.z); acc.w = fmaf(p, v.w, acc.w);
    }
    if (ls == 0) {
        float p = g_probs[b * L1P + LL];
        float4 v = reinterpret_cast<const float4*>(g_cKVn + b * CKV)[tid];
        acc.x = fmaf(p, v.x, acc.x); acc.y = fmaf(p, v.y, acc.y);
        acc.z = fmaf(p, v.z, acc.z); acc.w = fmaf(p, v.w, acc.w);
    }
    atomicAdd(&g_wsum[b * CKV + tid * 4 + 0], acc.x);
    atomicAdd(&g_wsum[b * CKV + tid * 4 + 1], acc.y);
    atomicAdd(&g_wsum[b * CKV + tid * 4 + 2], acc.z);
    atomicAdd(&g_wsum[b * CKV + tid * 4 + 3], acc.w);
}

// ---------------- launch ----------------
extern "C" void kernel_launch(void* const* d_in, const int* in_sizes, int n_in,
                              void* d_out, int out_size) {
    const float* h     = (const float*)d_in[0];   // [16,1,4096]
    const float* cKV   = (const float*)d_in[1];   // [16,2048,512]
    const float* kRc   = (const float*)d_in[2];   // [16,2048,2048]
    const float* W_DQ  = (const float*)d_in[3];   // [4096,1536]
    const float* W_DKV = (const float*)d_in[4];   // [4096,512]
    const float* W_UQC = (const float*)d_in[5];   // [1536,4096]
    const float* W_UQR = (const float*)d_in[6];   // [1536,2048]
    const float* W_KR  = (const float*)d_in[7];   // [4096,2048]
    const float* W_UKC = (const float*)d_in[8];   // [512,4096]
    const float* W_UVC = (const float*)d_in[9];   // [512,4096]
    const float* W_O   = (const float*)d_in[10];  // [4096,4096]
    float* out = (float*)d_out;

    float *p_cQ, *p_qC, *p_qR, *p_kRn, *p_cKVn, *p_wsum, *p_v;
    cudaGetSymbolAddress((void**)&p_cQ,   g_cQ);
    cudaGetSymbolAddress((void**)&p_qC,   g_qC);
    cudaGetSymbolAddress((void**)&p_qR,   g_qR);
    cudaGetSymbolAddress((void**)&p_kRn,  g_kRn);
    cudaGetSymbolAddress((void**)&p_cKVn, g_cKVn);
    cudaGetSymbolAddress((void**)&p_wsum, g_wsum);
    cudaGetSymbolAddress((void**)&p_v,    g_v);

    zero_kernel<<<128, 256>>>(out);

    // cQ = h @ W_DQ            (K=4096, N=1536)
    gemm_xw<<<dim3(3, 32),  128>>>(h,     W_DQ,  p_cQ,   4096, 1536, 128);
    // kR_new = h @ W_KR        (RoPE at pos 0 is identity)
    gemm_xw<<<dim3(4, 32),  128>>>(h,     W_KR,  p_kRn,  4096, 2048, 128);
    // cKV_new = h @ W_DKV
    gemm_xw<<<dim3(1, 32),  128>>>(h,     W_DKV, p_cKVn, 4096, 512,  128);
    // qC = cQ @ W_UQ_C
    gemm_xw<<<dim3(8, 24),  128>>>(p_cQ,  W_UQC, p_qC,   1536, 4096, 64);
    // qR = cQ @ W_UQ_R         (RoPE identity)
    gemm_xw<<<dim3(4, 24),  128>>>(p_cQ,  W_UQR, p_qR,   1536, 2048, 64);
    // qC_eff = qC @ W_UK_C^T
    qceff_kernel<<<dim3(64, 16), 256>>>(W_UKC);
    // prefix scores + cache copy (the HBM-heavy kernel)
    score_copy<<<dim3(256, 16), 256>>>(cKV, kRc, out);
    // new-token score + new cache rows
    newtoken_kernel<<<16, 256>>>(out);
    // softmax over 2049
    softmax_kernel<<<16, 256>>>();
    // probs-weighted cKV
    wsum_kernel<<<dim3(16, 16), 128>>>(cKV);
    // v = wsum @ W_UV_C        (K=512, N=4096)
    gemm_xw<<<dim3(8, 16),  128>>>(p_wsum, W_UVC, p_v, 512,  4096, 32);
    // out[:,0:4096] = v @ W_O  (K=4096, N=4096)
    gemm_xw<<<dim3(8, 32),  128>>>(p_v,    W_O,   out, 4096, 4096, 128);
}

// round 2
// speedup vs baseline: 1.0803x; 1.0803x over previous
#include <cuda_runtime.h>
#include <math.h>

#define Bb 16
#define LL 2048
#define HID 4096
#define CQ 1536
#define CKV 512
#define HH 32
#define DH 128
#define DR 64
#define HDR (HH*DR)   // 2048
#define HDH (HH*DH)   // 4096
#define L1P (LL+1)    // 2049

// out layout: [output 16*4096][new_cKV 16*2049*512][new_kR 16*2049*2048]
#define OFF_CKV (Bb*HID)
#define OFF_KR  (OFF_CKV + Bb*L1P*CKV)

typedef unsigned long long ull;

// ---------------- scratch ----------------
__device__ __align__(16) float g_cQ  [Bb*CQ];
__device__ __align__(16) float g_qC  [Bb*HDH];
__device__ __align__(16) float g_qR  [Bb*HDR];
__device__ __align__(16) float g_kRn [Bb*HDR];
__device__ __align__(16) float g_cKVn[Bb*CKV];
__device__ __align__(16) float g_qCeff[Bb*CKV];
__device__ __align__(16) float g_scores[Bb*L1P];
__device__ __align__(16) float g_probs [Bb*L1P];
__device__ __align__(16) float g_wsum[Bb*CKV];
__device__ __align__(16) float g_v   [Bb*HDH];

// ---------------- f32x2 helpers ----------------
__device__ __forceinline__ void fma2(ull& d, ull a, ull b) {
    asm("fma.rn.f32x2 %0, %1, %2, %0;" : "+l"(d) : "l"(a), "l"(b));
}
__device__ __forceinline__ ull pack2(float lo, float hi) {
    ull r; asm("mov.b64 %0, {%1, %2};" : "=l"(r) : "f"(lo), "f"(hi)); return r;
}
__device__ __forceinline__ void unpack2(ull v, float& lo, float& hi) {
    asm("mov.b64 {%0, %1}, %2;" : "=f"(lo), "=f"(hi) : "l"(v));
}

// ---------------- zero scratch + output head ----------------
__global__ void zero_kernel(float* __restrict__ out) {
    int t = blockIdx.x * blockDim.x + threadIdx.x;
    int T = gridDim.x * blockDim.x;
    for (int i = t; i < Bb*CQ;  i += T) g_cQ[i]  = 0.f;
    for (int i = t; i < Bb*HDH; i += T) g_qC[i]  = 0.f;
    for (int i = t; i < Bb*HDR; i += T) g_qR[i]  = 0.f;
    for (int i = t; i < Bb*HDR; i += T) g_kRn[i] = 0.f;
    for (int i = t; i < Bb*CKV; i += T) g_cKVn[i]= 0.f;
    for (int i = t; i < Bb*CKV; i += T) g_wsum[i]= 0.f;
    for (int i = t; i < Bb*HDH; i += T) g_v[i]   = 0.f;
    for (int i = t; i < Bb*HID; i += T) out[i]   = 0.f;
}

// ---------------- split-K skinny GEMM: out[16,N] += X[16,K] @ W[K,N] ----------------
// block 128 thr, thread -> 4 consecutive cols (512 cols/block).
// Batch-16 handled as 8 packed f32x2 pairs; X staged pre-packed in shared.
__global__ void gemm_xw(const float* __restrict__ X, const float* __restrict__ W,
                        float* __restrict__ out, int K, int N, int Kper)
{
    __shared__ ull sp[32*8];                // [k][bpair]
    ulonglong2* sp2 = reinterpret_cast<ulonglong2*>(sp);
    int n = (blockIdx.x * 128 + threadIdx.x) * 4;
    int kb = blockIdx.y * Kper;

    ull acc[4][8];
#pragma unroll
    for (int c = 0; c < 4; c++)
#pragma unroll
        for (int p = 0; p < 8; p++) acc[c][p] = 0ull;

    for (int k0 = kb; k0 < kb + Kper; k0 += 32) {
        for (int i = threadIdx.x; i < 256; i += 128) {
            int k = i >> 3, bp = i & 7;
            sp[k*8 + bp] = pack2(X[(2*bp)*K + k0 + k], X[(2*bp+1)*K + k0 + k]);
        }
        __syncthreads();
        if (n < N) {
            const float* Wp = W + (size_t)k0 * N + n;
#pragma unroll 8
            for (int k = 0; k < 32; k++) {
                float4 w4 = *reinterpret_cast<const float4*>(Wp + (size_t)k * N);
                ull wx = pack2(w4.x, w4.x), wy = pack2(w4.y, w4.y);
                ull wz = pack2(w4.z, w4.z), ww = pack2(w4.w, w4.w);
#pragma unroll
                for (int j = 0; j < 4; j++) {
                    ulonglong2 xp = sp2[k*4 + j];
                    int p0 = 2*j, p1 = 2*j + 1;
                    fma2(acc[0][p0], xp.x, wx); fma2(acc[0][p1], xp.y, wx);
                    fma2(acc[1][p0], xp.x, wy); fma2(acc[1][p1], xp.y, wy);
                    fma2(acc[2][p0], xp.x, wz); fma2(acc[2][p1], xp.y, wz);
                    fma2(acc[3][p0], xp.x, ww); fma2(acc[3][p1], xp.y, ww);
                }
            }
        }
        __syncthreads();
    }
    if (n < N) {
#pragma unroll
        for (int c = 0; c < 4; c++)
#pragma unroll
            for (int p = 0; p < 8; p++) {
                float lo, hi; unpack2(acc[c][p], lo, hi);
                atomicAdd(&out[(2*p)   * N + n + c], lo);
                atomicAdd(&out[(2*p+1) * N + n + c], hi);
            }
    }
}

// ---------------- qC_eff[b,n] = dot(qC[b,:4096], W_UK_C[n,:4096]) ----------------
__global__ void qceff_kernel(const float* __restrict__ Wukc) {
    int b = blockIdx.y;
    int wid = threadIdx.x >> 5, lane = threadIdx.x & 31;
    __shared__ float4 sq[HDH / 4];
    for (int i = threadIdx.x; i < HDH / 4; i += blockDim.x)
        sq[i] = reinterpret_cast<const float4*>(g_qC + b * HDH)[i];
    __syncthreads();
    int n = blockIdx.x * 8 + wid;
    const float4* w4 = reinterpret_cast<const float4*>(Wukc + (size_t)n * HDH);
    float sum = 0.f;
    for (int j = lane; j < HDH / 4; j += 32) {
        float4 a = sq[j], w = w4[j];
        sum += a.x * w.x + a.y * w.y + a.z * w.z + a.w * w.w;
    }
#pragma unroll
    for (int o = 16; o; o >>= 1) sum += __shfl_xor_sync(0xffffffffu, sum, o);
    if (lane == 0) g_qCeff[b * CKV + n] = sum;
}

// ---------------- fused: prefix scores + cache concat/copy ----------------
__global__ void score_copy(const float* __restrict__ cKV, const float* __restrict__ kRc,
                           float* __restrict__ out)
{
    int b = blockIdx.y;
    int wid = threadIdx.x >> 5, lane = threadIdx.x & 31;
    __shared__ float4 sq[(CKV + HDR) / 4];
    for (int i = threadIdx.x; i < CKV / 4; i += blockDim.x)
        sq[i] = reinterpret_cast<const float4*>(g_qCeff + b * CKV)[i];
    for (int i = threadIdx.x; i < HDR / 4; i += blockDim.x)
        sq[CKV / 4 + i] = reinterpret_cast<const float4*>(g_qR + b * HDR)[i];
    __syncthreads();

    int l = blockIdx.x * 8 + wid;
    const float4* c4  = reinterpret_cast<const float4*>(cKV + ((size_t)b * LL + l) * CKV);
    const float4* r4  = reinterpret_cast<const float4*>(kRc + ((size_t)b * LL + l) * HDR);
    float4* oc = reinterpret_cast<float4*>(out + (size_t)OFF_CKV + ((size_t)b * L1P + l) * CKV);
    float4* orr= reinterpret_cast<float4*>(out + (size_t)OFF_KR  + ((size_t)b * L1P + l) * HDR);

    float sum = 0.f;
#pragma unroll
    for (int j = 0; j < (CKV / 4) / 32; j++) {
        int idx = lane + j * 32;
        float4 v = c4[idx]; oc[idx] = v;
        float4 q = sq[idx];
        sum += v.x * q.x + v.y * q.y + v.z * q.z + v.w * q.w;
    }
#pragma unroll
    for (int j = 0; j < (HDR / 4) / 32; j++) {
        int idx = lane + j * 32;
        float4 v = r4[idx]; orr[idx] = v;
        float4 q = sq[CKV / 4 + idx];
        sum += v.x * q.x + v.y * q.y + v.z * q.z + v.w * q.w;
    }
#pragma unroll
    for (int o = 16; o; o >>= 1) sum += __shfl_xor_sync(0xffffffffu, sum, o);
    if (lane == 0) g_scores[b * L1P + l] = sum;
}

// ---------------- new-token score + new cache rows ----------------
__global__ void newtoken_kernel(float* __restrict__ out) {
    int b = blockIdx.x, tid = threadIdx.x;
    __shared__ float red[256];
    float sum = 0.f;
    for (int i = tid; i < CKV; i += 256) {
        float v = g_cKVn[b * CKV + i];
        out[(size_t)OFF_CKV + ((size_t)b * L1P + LL) * CKV + i] = v;
        sum += v * g_qCeff[b * CKV + i];
    }
    for (int i = tid; i < HDR; i += 256) {
        float v = g_kRn[b * HDR + i];
        out[(size_t)OFF_KR + ((size_t)b * L1P + LL) * HDR + i] = v;
        sum += v * g_qR[b * HDR + i];
    }
    red[tid] = sum; __syncthreads();
    for (int s = 128; s; s >>= 1) { if (tid < s) red[tid] += red[tid + s]; __syncthreads(); }
    if (tid == 0) g_scores[b * L1P + LL] = red[0];
}

// ---------------- softmax over 2049 ----------------
__global__ void softmax_kernel() {
    int b = blockIdx.x, tid = threadIdx.x;
    __shared__ float red[256];
    const float scale = rsqrtf((float)(DH + DR));
    float m = -1e30f;
    for (int i = tid; i < L1P; i += 256) m = fmaxf(m, g_scores[b * L1P + i] * scale);
    red[tid] = m; __syncthreads();
    for (int s = 128; s; s >>= 1) { if (tid < s) red[tid] = fmaxf(red[tid], red[tid + s]); __syncthreads(); }
    m = red[0]; __syncthreads();
    float sum = 0.f;
    for (int i = tid; i < L1P; i += 256) {
        float e = expf(g_scores[b * L1P + i] * scale - m);
        g_probs[b * L1P + i] = e;
        sum += e;
    }
    red[tid] = sum; __syncthreads();
    for (int s = 128; s; s >>= 1) { if (tid < s) red[tid] += red[tid + s]; __syncthreads(); }
    float inv = 1.f / red[0];
    __syncthreads();
    for (int i = tid; i < L1P; i += 256) g_probs[b * L1P + i] *= inv;
}

// ---------------- probs-weighted cKV sum ----------------
__global__ void wsum_kernel(const float* __restrict__ cKV) {
    int b = blockIdx.x, ls = blockIdx.y, tid = threadIdx.x;
    const float4* c4 = reinterpret_cast<const float4*>(cKV + (size_t)b * LL * CKV);
    float4 acc = make_float4(0.f, 0.f, 0.f, 0.f);
    int l0 = ls * (LL / 16);
#pragma unroll 4
    for (int l = l0; l < l0 + LL / 16; l++) {
        float p = g_probs[b * L1P + l];
        float4 v = c4[(size_t)l * (CKV / 4) + tid];
        acc.x = fmaf(p, v.x, acc.x); acc.y = fmaf(p, v.y, acc.y);
        acc.z = fmaf(p, v.z, acc.z); acc.w = fmaf(p, v.w, acc.w);
    }
    if (ls == 0) {
        float p = g_probs[b * L1P + LL];
        float4 v = reinterpret_cast<const float4*>(g_cKVn + b * CKV)[tid];
        acc.x = fmaf(p, v.x, acc.x); acc.y = fmaf(p, v.y, acc.y);
        acc.z = fmaf(p, v.z, acc.z); acc.w = fmaf(p, v.w, acc.w);
    }
    atomicAdd(&g_wsum[b * CKV + tid * 4 + 0], acc.x);
    atomicAdd(&g_wsum[b * CKV + tid * 4 + 1], acc.y);
    atomicAdd(&g_wsum[b * CKV + tid * 4 + 2], acc.z);
    atomicAdd(&g_wsum[b * CKV + tid * 4 + 3], acc.w);
}

// ---------------- launch ----------------
extern "C" void kernel_launch(void* const* d_in, const int* in_sizes, int n_in,
                              void* d_out, int out_size) {
    const float* h     = (const float*)d_in[0];
    const float* cKV   = (const float*)d_in[1];
    const float* kRc   = (const float*)d_in[2];
    const float* W_DQ  = (const float*)d_in[3];
    const float* W_DKV = (const float*)d_in[4];
    const float* W_UQC = (const float*)d_in[5];
    const float* W_UQR = (const float*)d_in[6];
    const float* W_KR  = (const float*)d_in[7];
    const float* W_UKC = (const float*)d_in[8];
    const float* W_UVC = (const float*)d_in[9];
    const float* W_O   = (const float*)d_in[10];
    float* out = (float*)d_out;

    float *p_cQ, *p_qC, *p_qR, *p_kRn, *p_cKVn, *p_wsum, *p_v;
    cudaGetSymbolAddress((void**)&p_cQ,   g_cQ);
    cudaGetSymbolAddress((void**)&p_qC,   g_qC);
    cudaGetSymbolAddress((void**)&p_qR,   g_qR);
    cudaGetSymbolAddress((void**)&p_kRn,  g_kRn);
    cudaGetSymbolAddress((void**)&p_cKVn, g_cKVn);
    cudaGetSymbolAddress((void**)&p_wsum, g_wsum);
    cudaGetSymbolAddress((void**)&p_v,    g_v);

    zero_kernel<<<128, 256>>>(out);

    // cQ = h @ W_DQ          (K=4096, N=1536): 3x64 = 192 blocks, dup 64
    gemm_xw<<<dim3(3, 64),  128>>>(h,     W_DQ,  p_cQ,   4096, 1536, 64);
    // kR_new = h @ W_KR      (RoPE at pos 0 = identity): 4x64 = 256 blocks
    gemm_xw<<<dim3(4, 64),  128>>>(h,     W_KR,  p_kRn,  4096, 2048, 64);
    // cKV_new = h @ W_DKV    : 1x128 = 128 blocks
    gemm_xw<<<dim3(1, 128), 128>>>(h,     W_DKV, p_cKVn, 4096, 512,  32);
    // qC = cQ @ W_UQ_C       : 8x24 = 192 blocks
    gemm_xw<<<dim3(8, 24),  128>>>(p_cQ,  W_UQC, p_qC,   1536, 4096, 64);
    // qR = cQ @ W_UQ_R       : 4x48 = 192 blocks
    gemm_xw<<<dim3(4, 48),  128>>>(p_cQ,  W_UQR, p_qR,   1536, 2048, 32);
    // qC_eff = qC @ W_UK_C^T
    qceff_kernel<<<dim3(64, 16), 256>>>(W_UKC);
    // prefix scores + cache copy (HBM-heavy)
    score_copy<<<dim3(256, 16), 256>>>(cKV, kRc, out);
    // new-token score + new cache rows
    newtoken_kernel<<<16, 256>>>(out);
    // softmax
    softmax_kernel<<<16, 256>>>();
    // probs-weighted cKV
    wsum_kernel<<<dim3(16, 16), 128>>>(cKV);
    // v = wsum @ W_UV_C      : 8x16 = 128 blocks
    gemm_xw<<<dim3(8, 16),  128>>>(p_wsum, W_UVC, p_v, 512,  4096, 32);
    // out = v @ W_O          : 8x32 = 256 blocks, dup 32
    gemm_xw<<<dim3(8, 32),  128>>>(p_v,    W_O,   out, 4096, 4096, 128);
}

// round 3
// speedup vs baseline: 1.1862x; 1.0980x over previous
#include <cuda_runtime.h>
#include <math.h>

#define Bb 16
#define LL 2048
#define HID 4096
#define CQ 1536
#define CKV 512
#define HH 32
#define DH 128
#define DR 64
#define HDR (HH*DR)   // 2048
#define HDH (HH*DH)   // 4096
#define L1P (LL+1)    // 2049

#define OFF_CKV (Bb*HID)
#define OFF_KR  (OFF_CKV + Bb*L1P*CKV)

typedef unsigned long long ull;

// ---------------- scratch ----------------
__device__ __align__(16) float g_cQ  [Bb*CQ];
__device__ __align__(16) float g_qC  [Bb*HDH];
__device__ __align__(16) float g_qR  [Bb*HDR];
__device__ __align__(16) float g_kRn [Bb*HDR];
__device__ __align__(16) float g_cKVn[Bb*CKV];
__device__ __align__(16) float g_qCeff[Bb*CKV];
__device__ __align__(16) float g_scores[Bb*L1P];
__device__ __align__(16) float g_probs [Bb*L1P];
__device__ __align__(16) float g_wsum[Bb*CKV];
__device__ __align__(16) float g_v   [Bb*HDH];

// ---------------- f32x2 helpers ----------------
__device__ __forceinline__ void fma2(ull& d, ull a, ull b) {
    asm("fma.rn.f32x2 %0, %1, %2, %0;" : "+l"(d) : "l"(a), "l"(b));
}
__device__ __forceinline__ ull pack2(float lo, float hi) {
    ull r; asm("mov.b64 %0, {%1, %2};" : "=l"(r) : "f"(lo), "f"(hi)); return r;
}
__device__ __forceinline__ void unpack2(ull v, float& lo, float& hi) {
    asm("mov.b64 {%0, %1}, %2;" : "=f"(lo), "=f"(hi) : "l"(v));
}

// ---------------- zero scratch + output head ----------------
__global__ void zero_kernel(float* __restrict__ out) {
    int t = blockIdx.x * blockDim.x + threadIdx.x;
    int T = gridDim.x * blockDim.x;
    for (int i = t; i < Bb*CQ;  i += T) g_cQ[i]  = 0.f;
    for (int i = t; i < Bb*HDH; i += T) g_qC[i]  = 0.f;
    for (int i = t; i < Bb*HDR; i += T) g_qR[i]  = 0.f;
    for (int i = t; i < Bb*HDR; i += T) g_kRn[i] = 0.f;
    for (int i = t; i < Bb*CKV; i += T) g_cKVn[i]= 0.f;
    for (int i = t; i < Bb*CKV; i += T) g_wsum[i]= 0.f;
    for (int i = t; i < Bb*HDH; i += T) g_v[i]   = 0.f;
    for (int i = t; i < Bb*HID; i += T) out[i]   = 0.f;
}

// ---------------- split-K skinny GEMM: out[16,N] += X[16,K] @ W[K,N] ----------------
// 128 threads, thread -> 4 consecutive cols (512-col tile).
// X for the whole K-slice staged in shared ONCE (pre-packed f32x2 batch pairs).
// W loads software-pipelined 8-deep for guaranteed MLP.
__global__ void __launch_bounds__(128) gemm_xw(
    const float* __restrict__ X, const float* __restrict__ W,
    float* __restrict__ out, int K, int N, int Kper)
{
    __shared__ ull sp[128*8];                 // [k][bpair], Kper <= 128
    int tid = threadIdx.x;
    int kb = blockIdx.y * Kper;

    for (int i = tid; i < Kper*8; i += 128) {
        int k = i >> 3, bp = i & 7;
        sp[i] = pack2(X[(2*bp)*K + kb + k], X[(2*bp+1)*K + kb + k]);
    }
    __syncthreads();

    int n = (blockIdx.x * 128 + tid) * 4;
    if (n >= N) return;

    ull acc[4][8];
#pragma unroll
    for (int c = 0; c < 4; c++)
#pragma unroll
        for (int p = 0; p < 8; p++) acc[c][p] = 0ull;

    const float* Wb = W + (size_t)kb * N + n;
    for (int k0 = 0; k0 < Kper; k0 += 8) {
        float4 w[8];
#pragma unroll
        for (int i = 0; i < 8; i++)
            w[i] = *reinterpret_cast<const float4*>(Wb + (size_t)(k0 + i) * N);
#pragma unroll
        for (int i = 0; i < 8; i++) {
            ull wx = pack2(w[i].x, w[i].x), wy = pack2(w[i].y, w[i].y);
            ull wz = pack2(w[i].z, w[i].z), ww = pack2(w[i].w, w[i].w);
            const ull* xk = &sp[(k0 + i) * 8];
#pragma unroll
            for (int p = 0; p < 8; p++) {
                ull xp = xk[p];
                fma2(acc[0][p], xp, wx);
                fma2(acc[1][p], xp, wy);
                fma2(acc[2][p], xp, wz);
                fma2(acc[3][p], xp, ww);
            }
        }
    }

#pragma unroll
    for (int c = 0; c < 4; c++)
#pragma unroll
        for (int p = 0; p < 8; p++) {
            float lo, hi; unpack2(acc[c][p], lo, hi);
            atomicAdd(&out[(2*p)   * N + n + c], lo);
            atomicAdd(&out[(2*p+1) * N + n + c], hi);
        }
}

// ---------------- qC_eff[b,n] = dot(qC[b,:4096], W_UK_C[n,:4096]) ----------------
__global__ void qceff_kernel(const float* __restrict__ Wukc) {
    int b = blockIdx.y;
    int wid = threadIdx.x >> 5, lane = threadIdx.x & 31;
    __shared__ float4 sq[HDH / 4];
    for (int i = threadIdx.x; i < HDH / 4; i += blockDim.x)
        sq[i] = reinterpret_cast<const float4*>(g_qC + b * HDH)[i];
    __syncthreads();
    int n = blockIdx.x * 8 + wid;
    const float4* w4 = reinterpret_cast<const float4*>(Wukc + (size_t)n * HDH);
    float sum = 0.f;
#pragma unroll 8
    for (int j = lane; j < HDH / 4; j += 32) {
        float4 a = sq[j], w = w4[j];
        sum += a.x * w.x + a.y * w.y + a.z * w.z + a.w * w.w;
    }
#pragma unroll
    for (int o = 16; o; o >>= 1) sum += __shfl_xor_sync(0xffffffffu, sum, o);
    if (lane == 0) g_qCeff[b * CKV + n] = sum;
}

// ---------------- fused: prefix scores + cache concat/copy ----------------
__global__ void score_copy(const float* __restrict__ cKV, const float* __restrict__ kRc,
                           float* __restrict__ out)
{
    int b = blockIdx.y;
    int wid = threadIdx.x >> 5, lane = threadIdx.x & 31;
    __shared__ float4 sq[(CKV + HDR) / 4];
    for (int i = threadIdx.x; i < CKV / 4; i += blockDim.x)
        sq[i] = reinterpret_cast<const float4*>(g_qCeff + b * CKV)[i];
    for (int i = threadIdx.x; i < HDR / 4; i += blockDim.x)
        sq[CKV / 4 + i] = reinterpret_cast<const float4*>(g_qR + b * HDR)[i];
    __syncthreads();

    int l = blockIdx.x * 8 + wid;
    const float4* c4  = reinterpret_cast<const float4*>(cKV + ((size_t)b * LL + l) * CKV);
    const float4* r4  = reinterpret_cast<const float4*>(kRc + ((size_t)b * LL + l) * HDR);
    float4* oc = reinterpret_cast<float4*>(out + (size_t)OFF_CKV + ((size_t)b * L1P + l) * CKV);
    float4* orr= reinterpret_cast<float4*>(out + (size_t)OFF_KR  + ((size_t)b * L1P + l) * HDR);

    float sum = 0.f;
#pragma unroll
    for (int j = 0; j < (CKV / 4) / 32; j++) {
        int idx = lane + j * 32;
        float4 v = c4[idx]; oc[idx] = v;
        float4 q = sq[idx];
        sum += v.x * q.x + v.y * q.y + v.z * q.z + v.w * q.w;
    }
#pragma unroll
    for (int j = 0; j < (HDR / 4) / 32; j++) {
        int idx = lane + j * 32;
        float4 v = r4[idx]; orr[idx] = v;
        float4 q = sq[CKV / 4 + idx];
        sum += v.x * q.x + v.y * q.y + v.z * q.z + v.w * q.w;
    }
#pragma unroll
    for (int o = 16; o; o >>= 1) sum += __shfl_xor_sync(0xffffffffu, sum, o);
    if (lane == 0) g_scores[b * L1P + l] = sum;
}

// ---------------- new-token score + new cache rows ----------------
__global__ void newtoken_kernel(float* __restrict__ out) {
    int b = blockIdx.x, tid = threadIdx.x;
    __shared__ float red[256];
    float sum = 0.f;
    for (int i = tid; i < CKV; i += 256) {
        float v = g_cKVn[b * CKV + i];
        out[(size_t)OFF_CKV + ((size_t)b * L1P + LL) * CKV + i] = v;
        sum += v * g_qCeff[b * CKV + i];
    }
    for (int i = tid; i < HDR; i += 256) {
        float v = g_kRn[b * HDR + i];
        out[(size_t)OFF_KR + ((size_t)b * L1P + LL) * HDR + i] = v;
        sum += v * g_qR[b * HDR + i];
    }
    red[tid] = sum; __syncthreads();
    for (int s = 128; s; s >>= 1) { if (tid < s) red[tid] += red[tid + s]; __syncthreads(); }
    if (tid == 0) g_scores[b * L1P + LL] = red[0];
}

// ---------------- softmax over 2049 ----------------
__global__ void softmax_kernel() {
    int b = blockIdx.x, tid = threadIdx.x;
    __shared__ float red[256];
    const float scale = rsqrtf((float)(DH + DR));
    float m = -1e30f;
    for (int i = tid; i < L1P; i += 256) m = fmaxf(m, g_scores[b * L1P + i] * scale);
    red[tid] = m; __syncthreads();
    for (int s = 128; s; s >>= 1) { if (tid < s) red[tid] = fmaxf(red[tid], red[tid + s]); __syncthreads(); }
    m = red[0]; __syncthreads();
    float sum = 0.f;
    for (int i = tid; i < L1P; i += 256) {
        float e = expf(g_scores[b * L1P + i] * scale - m);
        g_probs[b * L1P + i] = e;
        sum += e;
    }
    red[tid] = sum; __syncthreads();
    for (int s = 128; s; s >>= 1) { if (tid < s) red[tid] += red[tid + s]; __syncthreads(); }
    float inv = 1.f / red[0];
    __syncthreads();
    for (int i = tid; i < L1P; i += 256) g_probs[b * L1P + i] *= inv;
}

// ---------------- probs-weighted cKV sum ----------------
__global__ void wsum_kernel(const float* __restrict__ cKV) {
    int b = blockIdx.x, ls = blockIdx.y, tid = threadIdx.x;
    const float4* c4 = reinterpret_cast<const float4*>(cKV + (size_t)b * LL * CKV);
    float4 acc = make_float4(0.f, 0.f, 0.f, 0.f);
    int l0 = ls * (LL / 32);
#pragma unroll 8
    for (int l = l0; l < l0 + LL / 32; l++) {
        float p = g_probs[b * L1P + l];
        float4 v = c4[(size_t)l * (CKV / 4) + tid];
        acc.x = fmaf(p, v.x, acc.x); acc.y = fmaf(p, v.y, acc.y);
        acc.z = fmaf(p, v.z, acc.z); acc.w = fmaf(p, v.w, acc.w);
    }
    if (ls == 0) {
        float p = g_probs[b * L1P + LL];
        float4 v = reinterpret_cast<const float4*>(g_cKVn + b * CKV)[tid];
        acc.x = fmaf(p, v.x, acc.x); acc.y = fmaf(p, v.y, acc.y);
        acc.z = fmaf(p, v.z, acc.z); acc.w = fmaf(p, v.w, acc.w);
    }
    atomicAdd(&g_wsum[b * CKV + tid * 4 + 0], acc.x);
    atomicAdd(&g_wsum[b * CKV + tid * 4 + 1], acc.y);
    atomicAdd(&g_wsum[b * CKV + tid * 4 + 2], acc.z);
    atomicAdd(&g_wsum[b * CKV + tid * 4 + 3], acc.w);
}

// ---------------- launch ----------------
extern "C" void kernel_launch(void* const* d_in, const int* in_sizes, int n_in,
                              void* d_out, int out_size) {
    const float* h     = (const float*)d_in[0];
    const float* cKV   = (const float*)d_in[1];
    const float* kRc   = (const float*)d_in[2];
    const float* W_DQ  = (const float*)d_in[3];
    const float* W_DKV = (const float*)d_in[4];
    const float* W_UQC = (const float*)d_in[5];
    const float* W_UQR = (const float*)d_in[6];
    const float* W_KR  = (const float*)d_in[7];
    const float* W_UKC = (const float*)d_in[8];
    const float* W_UVC = (const float*)d_in[9];
    const float* W_O   = (const float*)d_in[10];
    float* out = (float*)d_out;

    float *p_cQ, *p_qC, *p_qR, *p_kRn, *p_cKVn, *p_wsum, *p_v;
    cudaGetSymbolAddress((void**)&p_cQ,   g_cQ);
    cudaGetSymbolAddress((void**)&p_qC,   g_qC);
    cudaGetSymbolAddress((void**)&p_qR,   g_qR);
    cudaGetSymbolAddress((void**)&p_kRn,  g_kRn);
    cudaGetSymbolAddress((void**)&p_cKVn, g_cKVn);
    cudaGetSymbolAddress((void**)&p_wsum, g_wsum);
    cudaGetSymbolAddress((void**)&p_v,    g_v);

    zero_kernel<<<128, 256>>>(out);

    // cQ = h @ W_DQ          : 3x64 = 192 blocks, dup 64
    gemm_xw<<<dim3(3, 64),  128>>>(h,     W_DQ,  p_cQ,   4096, 1536, 64);
    // kR_new = h @ W_KR      : 4x64 = 256 blocks, dup 64
    gemm_xw<<<dim3(4, 64),  128>>>(h,     W_KR,  p_kRn,  4096, 2048, 64);
    // cKV_new = h @ W_DKV    : 1x128 = 128 blocks, dup 128
    gemm_xw<<<dim3(1, 128), 128>>>(h,     W_DKV, p_cKVn, 4096, 512,  32);
    // qC = cQ @ W_UQ_C       : 8x24 = 192 blocks, dup 24
    gemm_xw<<<dim3(8, 24),  128>>>(p_cQ,  W_UQC, p_qC,   1536, 4096, 64);
    // qR = cQ @ W_UQ_R       : 4x48 = 192 blocks, dup 48
    gemm_xw<<<dim3(4, 48),  128>>>(p_cQ,  W_UQR, p_qR,   1536, 2048, 32);
    // qC_eff = qC @ W_UK_C^T
    qceff_kernel<<<dim3(64, 16), 256>>>(W_UKC);
    // prefix scores + cache copy (HBM-heavy)
    score_copy<<<dim3(256, 16), 256>>>(cKV, kRc, out);
    // new-token score + new cache rows
    newtoken_kernel<<<16, 256>>>(out);
    // softmax
    softmax_kernel<<<16, 256>>>();
    // probs-weighted cKV : 16x32 = 512 blocks
    wsum_kernel<<<dim3(16, 32), 128>>>(cKV);
    // v = wsum @ W_UV_C      : 8x16 = 128 blocks, dup 16
    gemm_xw<<<dim3(8, 16),  128>>>(p_wsum, W_UVC, p_v, 512,  4096, 32);
    // out = v @ W_O          : 8x64 = 512 blocks, dup 64
    gemm_xw<<<dim3(8, 64),  128>>>(p_v,    W_O,   out, 4096, 4096, 64);
}